// round 12
// baseline (speedup 1.0000x reference)
#include <cuda_runtime.h>
#include <math.h>

#define NT    4096
#define SEQ   128
#define DIN   32
#define DLAT  64
#define NU    256
#define INDIM 160
#define TM    32
#define NTH   256

typedef unsigned long long u64;
typedef ulonglong2 u64x2;

// ---------- packed f32x2 helpers ----------
__device__ __forceinline__ u64 bcast2(float a) {
    u64 r; asm("mov.b64 %0, {%1, %1};" : "=l"(r) : "f"(a)); return r;
}
__device__ __forceinline__ u64 pk2(float x, float y) {
    u64 r; asm("mov.b64 %0, {%1, %2};" : "=l"(r) : "f"(x), "f"(y)); return r;
}
__device__ __forceinline__ float2 unpk(u64 v) {
    float2 f; asm("mov.b64 {%0, %1}, %2;" : "=f"(f.x), "=f"(f.y) : "l"(v)); return f;
}
__device__ __forceinline__ void fma2(u64& d, u64 a, u64 b) {
    asm("fma.rn.f32x2 %0, %1, %2, %0;" : "+l"(d) : "l"(a), "l"(b));
}
__device__ __forceinline__ u64 mul2(u64 a, u64 b) {
    u64 d; asm("mul.rn.f32x2 %0, %1, %2;" : "=l"(d) : "l"(a), "l"(b)); return d;
}
// fast activations: __expf err ~2^-22, fully branchless, safe at +/-inf
__device__ __forceinline__ float tanh_f(float x) {
    return 1.0f - __fdividef(2.0f, __expf(2.0f * x) + 1.0f);
}
__device__ __forceinline__ float sigmoid_f(float x) {
    return __fdividef(1.0f, 1.0f + __expf(-x));
}

// ---------- cp.async helpers ----------
__device__ __forceinline__ void cpa16(unsigned d, const float* s) {
    asm volatile("cp.async.cg.shared.global [%0], [%1], 16;" :: "r"(d), "l"(s));
}
#define CPCOMMIT() asm volatile("cp.async.commit_group;")
#define CPWAIT1()  asm volatile("cp.async.wait_group 1;")
#define CPWAIT0()  asm volatile("cp.async.wait_group 0;")

// 16KB slab from one source
__device__ __forceinline__ void copy16(float* dst, const float* __restrict__ src, int tid) {
    unsigned d = (unsigned)__cvta_generic_to_shared(dst) + tid * 16;
#pragma unroll
    for (int i = 0; i < 4; ++i) cpa16(d + i * 4096, src + tid * 4 + i * 1024);
}
// 8KB + 8KB from two sources
__device__ __forceinline__ void copy8x2(float* dst, const float* __restrict__ sa,
                                        const float* __restrict__ sb, int tid) {
    unsigned d = (unsigned)__cvta_generic_to_shared(dst) + tid * 16;
#pragma unroll
    for (int i = 0; i < 2; ++i) cpa16(d + i * 4096, sa + tid * 4 + i * 1024);
#pragma unroll
    for (int i = 0; i < 2; ++i) cpa16(d + 8192 + i * 4096, sb + tid * 4 + i * 1024);
}

__device__ __forceinline__ int nxt1(int c) { return (c == 2) ? 0 : c + 1; }
__device__ __forceinline__ int nxt2(int c) { return (c == 0) ? 2 : c - 1; }

// XI: 64-col pair layout for lvT/uT (elementwise-only buffers)
#define XI(c, p)  ((p)*128 + (((c)&1)*32 + ((c)>>1))*2)

// dup buffers: [feature k][row*2 (+0/+1 duplicated)]
struct Smem {
    float wbuf[3][4096];   // 3 x 16KB weight slabs
    float yT [DLAT * 64];  // dup
    float ycT[INDIM * 64]; // dup
    float ccT[INDIM * 64]; // dup
    float lvT[16 * 128];   // XI
    float uT [16 * 128];   // XI
    float h1A[16 * 512];   // row-pair packed
    float h1B[16 * 512];
    float ts[SEQ];
};

// ---------- first layer slab: zero-MOV (dup A, packed W col-pairs) ----------
// thread: rows 8rg..8rg+7, cols 4cg..4cg+3
template<int SK>
__device__ __forceinline__ void fl_slab(const float* __restrict__ Ad,
                                        const float* __restrict__ Ws,
                                        int kbase, u64 acc[4][4], int cg, int rg)
{
    const u64x2* Wp = reinterpret_cast<const u64x2*>(Ws) + cg;  // 64 u64x2 per k-row
    const float* Ab = Ad + kbase * 64 + 16 * rg;
#pragma unroll 4
    for (int kk = 0; kk < SK; ++kk) {
        u64x2 w = Wp[kk * 64];              // {w(c0),w(c0+1)} , {w(c0+2),w(c0+3)}
        const float* ap = Ab + kk * 64;
#pragma unroll
        for (int q = 0; q < 4; ++q) {
            u64x2 a = *reinterpret_cast<const u64x2*>(ap + 4 * q);  // {a(r),a(r)},{a(r+1),a(r+1)}
            fma2(acc[q][0], a.x, w.x); fma2(acc[q][1], a.x, w.y);
            fma2(acc[q][2], a.y, w.x); fma2(acc[q][3], a.y, w.y);
        }
    }
}

template<int SK>
__device__ __forceinline__ void fl_slab_dual(const float* __restrict__ Ad,
                                             const float* __restrict__ Wsu,
                                             const float* __restrict__ Wsr,
                                             int kbase, u64 aU[4][4], u64 aR[4][4],
                                             int cg, int rg)
{
    const u64x2* WU = reinterpret_cast<const u64x2*>(Wsu) + cg;
    const u64x2* WR = reinterpret_cast<const u64x2*>(Wsr) + cg;
    const float* Ab = Ad + kbase * 64 + 16 * rg;
#pragma unroll 4
    for (int kk = 0; kk < SK; ++kk) {
        u64x2 wu = WU[kk * 64];
        u64x2 wr = WR[kk * 64];
        const float* ap = Ab + kk * 64;
#pragma unroll
        for (int q = 0; q < 4; ++q) {
            u64x2 a = *reinterpret_cast<const u64x2*>(ap + 4 * q);
            fma2(aU[q][0], a.x, wu.x); fma2(aU[q][1], a.x, wu.y);
            fma2(aU[q][2], a.y, wu.x); fma2(aU[q][3], a.y, wu.y);
            fma2(aR[q][0], a.x, wr.x); fma2(aR[q][1], a.x, wr.y);
            fma2(aR[q][2], a.y, wr.x); fma2(aR[q][3], a.y, wr.y);
        }
    }
}

// first-layer epilogue: cross-pack cols->row-pairs, tanh, store h1
__device__ __forceinline__ void fl_epi(u64 acc[4][4], const float* __restrict__ bias,
                                       float* __restrict__ OT, int cg, int rg)
{
    float4 b4 = reinterpret_cast<const float4*>(bias)[cg];
#pragma unroll
    for (int q = 0; q < 4; ++q) {
        float2 lo01 = unpk(acc[q][0]), lo23 = unpk(acc[q][1]);
        float2 hi01 = unpk(acc[q][2]), hi23 = unpk(acc[q][3]);
        float* base = OT + (4 * rg + q) * 512 + cg * 2;
        *reinterpret_cast<u64*>(base)       = pk2(tanh_f(lo01.x + b4.x), tanh_f(hi01.x + b4.x));
        *reinterpret_cast<u64*>(base + 128) = pk2(tanh_f(lo01.y + b4.y), tanh_f(hi01.y + b4.y));
        *reinterpret_cast<u64*>(base + 256) = pk2(tanh_f(lo23.x + b4.z), tanh_f(hi23.x + b4.z));
        *reinterpret_cast<u64*>(base + 384) = pk2(tanh_f(lo23.y + b4.w), tanh_f(hi23.y + b4.w));
    }
}

// ---------- second layer slab: k-paired LDS.128 A reads ----------
// SR = k-rows in slab; K04 = global k0/4
template<int SR>
__device__ __forceinline__ void sl_slab(const float* __restrict__ A0,
                                        const float* __restrict__ A1,
                                        const float* __restrict__ Ws,
                                        int K04, int cp, u64 acc[2][2])
{
    const float2* W2 = reinterpret_cast<const float2*>(Ws) + cp;
#pragma unroll 2
    for (int te = 0; te < SR / 4; te += 2) {
#pragma unroll
        for (int j = 0; j < 4; ++j) {
            int o = (j * 64 + K04 + te) * 2;
            u64x2 a0 = *reinterpret_cast<const u64x2*>(A0 + o);  // pairs for k, k+4
            u64x2 a1 = *reinterpret_cast<const u64x2*>(A1 + o);
            float2 wA = W2[(4 * te + j) * 32];
            float2 wB = W2[(4 * te + 4 + j) * 32];
            u64 wAx = bcast2(wA.x), wAy = bcast2(wA.y);
            u64 wBx = bcast2(wB.x), wBy = bcast2(wB.y);
            fma2(acc[0][0], a0.x, wAx); fma2(acc[0][1], a0.x, wAy);
            fma2(acc[1][0], a1.x, wAx); fma2(acc[1][1], a1.x, wAy);
            fma2(acc[0][0], a0.y, wBx); fma2(acc[0][1], a0.y, wBy);
            fma2(acc[1][0], a1.y, wBx); fma2(acc[1][1], a1.y, wBy);
        }
    }
}

template<int SR>
__device__ __forceinline__ void sl_slab_dual(const float* __restrict__ Aa0,
                                             const float* __restrict__ Aa1,
                                             const float* __restrict__ Ab0,
                                             const float* __restrict__ Ab1,
                                             const float* __restrict__ Wsu,
                                             const float* __restrict__ Wsr,
                                             int K04, int cp,
                                             u64 aU[2][2], u64 aR[2][2])
{
    const float2* WU = reinterpret_cast<const float2*>(Wsu) + cp;
    const float2* WR = reinterpret_cast<const float2*>(Wsr) + cp;
#pragma unroll 2
    for (int te = 0; te < SR / 4; te += 2) {
#pragma unroll
        for (int j = 0; j < 4; ++j) {
            int o = (j * 64 + K04 + te) * 2;
            u64x2 pa0 = *reinterpret_cast<const u64x2*>(Aa0 + o);
            u64x2 pa1 = *reinterpret_cast<const u64x2*>(Aa1 + o);
            u64x2 pb0 = *reinterpret_cast<const u64x2*>(Ab0 + o);
            u64x2 pb1 = *reinterpret_cast<const u64x2*>(Ab1 + o);
            float2 uA = WU[(4 * te + j) * 32], uB = WU[(4 * te + 4 + j) * 32];
            float2 rA = WR[(4 * te + j) * 32], rB = WR[(4 * te + 4 + j) * 32];
            u64 uAx = bcast2(uA.x), uAy = bcast2(uA.y);
            u64 uBx = bcast2(uB.x), uBy = bcast2(uB.y);
            u64 rAx = bcast2(rA.x), rAy = bcast2(rA.y);
            u64 rBx = bcast2(rB.x), rBy = bcast2(rB.y);
            fma2(aU[0][0], pa0.x, uAx); fma2(aU[0][1], pa0.x, uAy);
            fma2(aU[1][0], pa1.x, uAx); fma2(aU[1][1], pa1.x, uAy);
            fma2(aU[0][0], pa0.y, uBx); fma2(aU[0][1], pa0.y, uBy);
            fma2(aU[1][0], pa1.y, uBx); fma2(aU[1][1], pa1.y, uBy);
            fma2(aR[0][0], pb0.x, rAx); fma2(aR[0][1], pb0.x, rAy);
            fma2(aR[1][0], pb1.x, rAx); fma2(aR[1][1], pb1.x, rAy);
            fma2(aR[0][0], pb0.y, rBx); fma2(aR[0][1], pb0.y, rBy);
            fma2(aR[1][0], pb1.y, rBx); fma2(aR[1][1], pb1.y, rBy);
        }
    }
}

// candidate layer 2 slab (N=128)
template<int SR>
__device__ __forceinline__ void f_slab(const float* __restrict__ A0,
                                       const float* __restrict__ A1,
                                       const float* __restrict__ Ws,
                                       int K04, int cp, u64 aS[2][2], u64 aD[2][2])
{
    const float2* W2 = reinterpret_cast<const float2*>(Ws);
#pragma unroll 2
    for (int te = 0; te < SR / 4; te += 2) {
#pragma unroll
        for (int j = 0; j < 4; ++j) {
            int o = (j * 64 + K04 + te) * 2;
            u64x2 a0 = *reinterpret_cast<const u64x2*>(A0 + o);
            u64x2 a1 = *reinterpret_cast<const u64x2*>(A1 + o);
            float2 wlA = W2[(4 * te + j) * 64 + cp],      whA = W2[(4 * te + j) * 64 + 32 + cp];
            float2 wlB = W2[(4 * te + 4 + j) * 64 + cp],  whB = W2[(4 * te + 4 + j) * 64 + 32 + cp];
            u64 lAx = bcast2(wlA.x), lAy = bcast2(wlA.y);
            u64 hAx = bcast2(whA.x), hAy = bcast2(whA.y);
            u64 lBx = bcast2(wlB.x), lBy = bcast2(wlB.y);
            u64 hBx = bcast2(whB.x), hBy = bcast2(whB.y);
            fma2(aS[0][0], a0.x, lAx); fma2(aS[0][1], a0.x, lAy);
            fma2(aS[1][0], a1.x, lAx); fma2(aS[1][1], a1.x, lAy);
            fma2(aD[0][0], a0.x, hAx); fma2(aD[0][1], a0.x, hAy);
            fma2(aD[1][0], a1.x, hAx); fma2(aD[1][1], a1.x, hAy);
            fma2(aS[0][0], a0.y, lBx); fma2(aS[0][1], a0.y, lBy);
            fma2(aS[1][0], a1.y, lBx); fma2(aS[1][1], a1.y, lBy);
            fma2(aD[0][0], a0.y, hBx); fma2(aD[0][1], a0.y, hBy);
            fma2(aD[1][0], a1.y, hBx); fma2(aD[1][1], a1.y, hBy);
        }
    }
}

__global__ __launch_bounds__(NTH, 1)
void ode_rnn_kernel(const float* __restrict__ data,
                    const float* __restrict__ tsteps,
                    const float* __restrict__ Wo1, const float* __restrict__ bo1,
                    const float* __restrict__ Wo2, const float* __restrict__ bo2,
                    const float* __restrict__ Wu1, const float* __restrict__ bu1,
                    const float* __restrict__ Wu2, const float* __restrict__ bu2,
                    const float* __restrict__ Wr1, const float* __restrict__ br1,
                    const float* __restrict__ Wr2, const float* __restrict__ br2,
                    const float* __restrict__ Wn1, const float* __restrict__ bn1,
                    const float* __restrict__ Wn2, const float* __restrict__ bn2,
                    float* __restrict__ out)
{
    extern __shared__ float smem_raw[];
    Smem* S = reinterpret_cast<Smem*>(smem_raw);
    const int tid = threadIdx.x;
    const int traj0 = blockIdx.x * TM;

    const int cg  = tid & 63;          // first-layer cols 4cg..4cg+3
    const int rg  = tid >> 6;          // first-layer rows 8rg..8rg+7
    const int cp  = tid & 31;          // second-layer col-pair
    const int rp0 = (tid >> 5) * 2;    // second-layer pairs rp0, rp0+1

    for (int i = tid; i < DLAT * 64; i += NTH) S->yT[i] = 0.f;
    for (int i = tid; i < 16 * 128; i += NTH) S->lvT[i] = 0.f;
    for (int i = tid; i < SEQ; i += NTH) S->ts[i] = tsteps[i];

    // pipeline prologue: first two 16KB slabs of Wo1
    copy16(S->wbuf[0], Wo1, tid);        CPCOMMIT();
    copy16(S->wbuf[1], Wo1 + 4096, tid); CPCOMMIT();
    int cb = 0;
    __syncthreads();

    const float* A0 = S->h1A + rp0 * 512;
    const float* A1 = A0 + 512;
    const float* B0 = S->h1B + rp0 * 512;
    const float* B1 = B0 + 512;

    for (int s = 0; s < SEQ - 1; ++s) {
        const float dt = (s == 0) ? (S->ts[1] - S->ts[0]) : (S->ts[s] - S->ts[s + 1]);

        // x prefetch (global); lv -> ycT dup cols [64:128) (same-thread RAW vs prev F epi)
        float xv[4];
#pragma unroll
        for (int e = 0; e < 4; ++e) {
            int idx = tid + e * NTH;
            int r = idx >> 5, c = idx & 31;
            xv[e] = data[(size_t)(traj0 + r) * SEQ * DIN + (size_t)(s + 1) * DIN + c];
        }
#pragma unroll
        for (int p = 0; p < 2; ++p)
#pragma unroll
            for (int j = 0; j < 2; ++j) {
                int c = 2 * cp + j, pr = rp0 + p;
                float2 l = unpk(*reinterpret_cast<const u64*>(S->lvT + XI(c, pr)));
                *reinterpret_cast<u64*>(S->ycT + (DLAT + c) * 64 + 4 * pr)     = bcast2(l.x);
                *reinterpret_cast<u64*>(S->ycT + (DLAT + c) * 64 + 4 * pr + 2) = bcast2(l.y);
            }

        // ===== Phase A: ODE L1 (4 slabs x 16k) =====
        u64 aA[4][4];
#pragma unroll
        for (int q = 0; q < 4; ++q) { aA[q][0]=0; aA[q][1]=0; aA[q][2]=0; aA[q][3]=0; }
#pragma unroll 1
        for (int i = 0; i < 4; ++i) {
            CPWAIT1(); __syncthreads();
            if (i < 2) copy16(S->wbuf[nxt2(cb)], Wo1 + (i + 2) * 4096, tid);
            else       copy16(S->wbuf[nxt2(cb)], Wo2 + (i - 2) * 4096, tid);
            CPCOMMIT();
            fl_slab<16>(S->yT, S->wbuf[cb], 16 * i, aA, cg, rg);
            if (i == 3) {
                fl_epi(aA, bo1, S->h1A, cg, rg);
#pragma unroll
                for (int e = 0; e < 4; ++e) {   // stage x -> ycT/ccT dup cols [128:160)
                    int idx = tid + e * NTH;
                    int r = idx >> 5, c = idx & 31;
                    u64 xd = bcast2(xv[e]);
                    *reinterpret_cast<u64*>(S->ycT + (2 * DLAT + c) * 64 + 2 * r) = xd;
                    *reinterpret_cast<u64*>(S->ccT + (2 * DLAT + c) * 64 + 2 * r) = xd;
                }
            }
            cb = nxt1(cb);
        }

        // ===== Phase B: ODE L2 (4 slabs x 64k) =====
        u64 aB[2][2];
        aB[0][0]=0; aB[0][1]=0; aB[1][0]=0; aB[1][1]=0;
#pragma unroll 1
        for (int i = 0; i < 4; ++i) {
            CPWAIT1(); __syncthreads();
            if (i < 2) copy16(S->wbuf[nxt2(cb)], Wo2 + (i + 2) * 4096, tid);
            else       copy8x2(S->wbuf[nxt2(cb)], Wu1 + (i - 2) * 2048, Wr1 + (i - 2) * 2048, tid);
            CPCOMMIT();
            sl_slab<64>(A0, A1, S->wbuf[cb], 16 * i, cp, aB);
            if (i == 3) {   // epilogue: ycT dup cols [0:64) = y + (o+b)*dt
                float2 bb = reinterpret_cast<const float2*>(bo2)[cp];
                float bj[2] = {bb.x, bb.y};
#pragma unroll
                for (int p = 0; p < 2; ++p)
#pragma unroll
                    for (int j = 0; j < 2; ++j) {
                        int c = 2 * cp + j, pr = rp0 + p;
                        float2 o = unpk(aB[p][j]);
                        u64x2 yd = *reinterpret_cast<const u64x2*>(S->yT + c * 64 + 4 * pr);
                        float rx = fmaf(o.x + bj[j], dt, unpk(yd.x).x);
                        float ry = fmaf(o.y + bj[j], dt, unpk(yd.y).x);
                        *reinterpret_cast<u64*>(S->ycT + c * 64 + 4 * pr)     = bcast2(rx);
                        *reinterpret_cast<u64*>(S->ycT + c * 64 + 4 * pr + 2) = bcast2(ry);
                    }
            }
            cb = nxt1(cb);
        }

        // ===== Phase C: update+reset L1 (20 dual slabs x 8k) =====
        u64 aU[4][4], aR[4][4];
#pragma unroll
        for (int q = 0; q < 4; ++q)
#pragma unroll
            for (int j = 0; j < 4; ++j) { aU[q][j] = 0; aR[q][j] = 0; }
#pragma unroll 1
        for (int ci = 0; ci < 20; ++ci) {
            CPWAIT1(); __syncthreads();
            if (ci < 18) copy8x2(S->wbuf[nxt2(cb)], Wu1 + (ci + 2) * 2048, Wr1 + (ci + 2) * 2048, tid);
            else         copy8x2(S->wbuf[nxt2(cb)], Wu2 + (ci - 18) * 2048, Wr2 + (ci - 18) * 2048, tid);
            CPCOMMIT();
            fl_slab_dual<8>(S->ycT, S->wbuf[cb], S->wbuf[cb] + 2048, 8 * ci, aU, aR, cg, rg);
            if (ci == 19) {
                fl_epi(aU, bu1, S->h1A, cg, rg);
                fl_epi(aR, br1, S->h1B, cg, rg);
            }
            cb = nxt1(cb);
        }

        // ===== Phase D: update+reset L2 (8 dual slabs x 32k) =====
        u64 dU[2][2], dR[2][2];
        dU[0][0]=0; dU[0][1]=0; dU[1][0]=0; dU[1][1]=0;
        dR[0][0]=0; dR[0][1]=0; dR[1][0]=0; dR[1][1]=0;
#pragma unroll 1
        for (int di = 0; di < 8; ++di) {
            CPWAIT1(); __syncthreads();
            if (di < 6) copy8x2(S->wbuf[nxt2(cb)], Wu2 + (di + 2) * 2048, Wr2 + (di + 2) * 2048, tid);
            else        copy16(S->wbuf[nxt2(cb)], Wn1 + (di - 6) * 4096, tid);
            CPCOMMIT();
            sl_slab_dual<32>(A0, A1, B0, B1, S->wbuf[cb], S->wbuf[cb] + 2048, 8 * di, cp, dU, dR);
            if (di == 7) {   // epilogue -> uT (XI), ccT dup cols [0:128)
                float2 bu = reinterpret_cast<const float2*>(bu2)[cp];
                float2 br = reinterpret_cast<const float2*>(br2)[cp];
                float buj[2] = {bu.x, bu.y};
                float brj[2] = {br.x, br.y};
#pragma unroll
                for (int p = 0; p < 2; ++p)
#pragma unroll
                    for (int j = 0; j < 2; ++j) {
                        int c = 2 * cp + j, pr = rp0 + p;
                        float2 vu = unpk(dU[p][j]);
                        *reinterpret_cast<u64*>(S->uT + XI(c, pr)) =
                            pk2(sigmoid_f(vu.x + buj[j]), sigmoid_f(vu.y + buj[j]));
                        float2 vr = unpk(dR[p][j]);
                        u64 r0d = bcast2(sigmoid_f(vr.x + brj[j]));
                        u64 r1d = bcast2(sigmoid_f(vr.y + brj[j]));
                        u64x2 ylo = *reinterpret_cast<const u64x2*>(S->ycT + c * 64 + 4 * pr);
                        u64x2 yhi = *reinterpret_cast<const u64x2*>(S->ycT + (c + DLAT) * 64 + 4 * pr);
                        *reinterpret_cast<u64*>(S->ccT + c * 64 + 4 * pr)              = mul2(ylo.x, r0d);
                        *reinterpret_cast<u64*>(S->ccT + c * 64 + 4 * pr + 2)          = mul2(ylo.y, r1d);
                        *reinterpret_cast<u64*>(S->ccT + (c + DLAT) * 64 + 4 * pr)     = mul2(yhi.x, r0d);
                        *reinterpret_cast<u64*>(S->ccT + (c + DLAT) * 64 + 4 * pr + 2) = mul2(yhi.y, r1d);
                    }
            }
            cb = nxt1(cb);
        }

        // ===== Phase E: candidate L1 (10 slabs x 16k) =====
        u64 aE[4][4];
#pragma unroll
        for (int q = 0; q < 4; ++q) { aE[q][0]=0; aE[q][1]=0; aE[q][2]=0; aE[q][3]=0; }
#pragma unroll 1
        for (int ei = 0; ei < 10; ++ei) {
            CPWAIT1(); __syncthreads();
            if (ei < 8) copy16(S->wbuf[nxt2(cb)], Wn1 + (ei + 2) * 4096, tid);
            else        copy16(S->wbuf[nxt2(cb)], Wn2 + (ei - 8) * 4096, tid);
            CPCOMMIT();
            fl_slab<16>(S->ccT, S->wbuf[cb], 16 * ei, aE, cg, rg);
            if (ei == 9) fl_epi(aE, bn1, S->h1A, cg, rg);
            cb = nxt1(cb);
        }

        // ===== Phase F: candidate L2 (8 slabs x 32k) + fused state update =====
        u64 fS[2][2], fD[2][2];
        fS[0][0]=0; fS[0][1]=0; fS[1][0]=0; fS[1][1]=0;
        fD[0][0]=0; fD[0][1]=0; fD[1][0]=0; fD[1][1]=0;
#pragma unroll 1
        for (int fi = 0; fi < 8; ++fi) {
            CPWAIT1(); __syncthreads();
            if (fi < 6) copy16(S->wbuf[nxt2(cb)], Wn2 + (fi + 2) * 4096, tid);
            else        copy16(S->wbuf[nxt2(cb)], Wo1 + (fi - 6) * 4096, tid);  // next-step A
            CPCOMMIT();
            f_slab<32>(A0, A1, S->wbuf[cb], 8 * fi, cp, fS, fD);
            if (fi == 7) {
                float2 bl = reinterpret_cast<const float2*>(bn2)[cp];
                float2 bh = *reinterpret_cast<const float2*>(bn2 + DLAT + 2 * cp);
                float blj[2] = {bl.x, bl.y};
                float bhj[2] = {bh.x, bh.y};
#pragma unroll
                for (int p = 0; p < 2; ++p)
#pragma unroll
                    for (int j = 0; j < 2; ++j) {
                        int c = 2 * cp + j, pr = rp0 + p;
                        float2 ns = unpk(fS[p][j]);
                        ns.x += blj[j]; ns.y += blj[j];
                        float2 nd = unpk(fD[p][j]);
                        nd.x = fabsf(nd.x + bhj[j]); nd.y = fabsf(nd.y + bhj[j]);
                        float2 uu = unpk(*reinterpret_cast<const u64*>(S->uT + XI(c, pr)));
                        u64x2 yod = *reinterpret_cast<const u64x2*>(S->ycT + c * 64 + 4 * pr);
                        float yo0 = unpk(yod.x).x, yo1 = unpk(yod.y).x;
                        float2 lo = unpk(*reinterpret_cast<const u64*>(S->lvT + XI(c, pr)));
                        float ny0 = (1.f - uu.x) * ns.x + uu.x * yo0;
                        float ny1 = (1.f - uu.y) * ns.y + uu.y * yo1;
                        float nl0 = (1.f - uu.x) * nd.x + uu.x * lo.x;
                        float nl1 = (1.f - uu.y) * nd.y + uu.y * lo.y;
                        *reinterpret_cast<u64*>(S->yT + c * 64 + 4 * pr)     = bcast2(ny0);
                        *reinterpret_cast<u64*>(S->yT + c * 64 + 4 * pr + 2) = bcast2(ny1);
                        *reinterpret_cast<u64*>(S->lvT + XI(c, pr)) = pk2(nl0, nl1);
                    }
            }
            cb = nxt1(cb);
        }
    }

    CPWAIT0(); __syncthreads();

    // ===== output: yi (4096x64) then yi_logvar (4096x64) =====
    for (int i = tid; i < TM * DLAT; i += NTH) {
        int r = i >> 6, c = i & 63;
        out[(size_t)(traj0 + r) * DLAT + c] = S->yT[c * 64 + 2 * r];
        out[(size_t)NT * DLAT + (size_t)(traj0 + r) * DLAT + c] = S->lvT[XI(c, r >> 1) + (r & 1)];
    }
}

extern "C" void kernel_launch(void* const* d_in, const int* in_sizes, int n_in,
                              void* d_out, int out_size) {
    const float* data = (const float*)d_in[0];
    const float* ts   = (const float*)d_in[1];
    const float* Wo1  = (const float*)d_in[2];
    const float* bo1  = (const float*)d_in[3];
    const float* Wo2  = (const float*)d_in[4];
    const float* bo2  = (const float*)d_in[5];
    const float* Wu1  = (const float*)d_in[6];
    const float* bu1  = (const float*)d_in[7];
    const float* Wu2  = (const float*)d_in[8];
    const float* bu2  = (const float*)d_in[9];
    const float* Wr1  = (const float*)d_in[10];
    const float* br1  = (const float*)d_in[11];
    const float* Wr2  = (const float*)d_in[12];
    const float* br2  = (const float*)d_in[13];
    const float* Wn1  = (const float*)d_in[14];
    const float* bn1  = (const float*)d_in[15];
    const float* Wn2  = (const float*)d_in[16];
    const float* bn2  = (const float*)d_in[17];
    float* out = (float*)d_out;

    const int smem = (int)sizeof(Smem);
    cudaFuncSetAttribute(ode_rnn_kernel,
                         cudaFuncAttributeMaxDynamicSharedMemorySize, smem);
    ode_rnn_kernel<<<NT / TM, NTH, smem>>>(
        data, ts, Wo1, bo1, Wo2, bo2, Wu1, bu1, Wu2, bu2,
        Wr1, br1, Wr2, br2, Wn1, bn1, Wn2, bn2, out);
}